// round 1
// baseline (speedup 1.0000x reference)
#include <cuda_runtime.h>
#include <cstddef>
#include <math.h>

#define HWSZ 16384
#define IMG 128
#define CB 128
#define C3 384
#define BATCH 8
#define HEADS 8

// ---------------- scratch (static device globals; no allocs) ----------------
__device__ float g_xq[(size_t)BATCH * C3 * HWSZ];      // [b][384][HW]
__device__ float g_D[(size_t)BATCH * 3 * C3 * HWSZ];   // [b][scale][384][HW]
__device__ float g_q[(size_t)BATCH * CB * HWSZ];       // [b][128][HW]
__device__ float g_k[(size_t)BATCH * CB * HWSZ];
__device__ float g_gram[BATCH * HEADS * 16 * 16];
__device__ float g_ssq[BATCH * HEADS * 16];
__device__ float g_ssk[BATCH * HEADS * 16];
__device__ float g_attn[BATCH * HEADS * 16 * 16];
__device__ float g_T1[BATCH * CB * C3];
__device__ float g_M[BATCH * CB * C3];

// ---------------- packed fp32x2 helpers (Blackwell f32x2 pipe) --------------
__device__ __forceinline__ unsigned long long pack2(float x) {
    unsigned long long r;
    asm("mov.b64 %0, {%1, %1};" : "=l"(r) : "f"(x));
    return r;
}
__device__ __forceinline__ void fma2(unsigned long long& d,
                                     unsigned long long a,
                                     unsigned long long b) {
    asm("fma.rn.f32x2 %0, %1, %2, %0;" : "+l"(d) : "l"(a), "l"(b));
}

// ---------------- generic SGEMM: C[b,m,n] = sum_r A[m,r] * Brow(r)[n] -------
// B row r of batch z lives at: Bb + z*bStrB + (r>>7)*sStr + (r&127)*HWSZ
// A (weights) at A + z*aStrB, row-major [M,K].
__global__ void __launch_bounds__(256)
sgemm_kernel(const float* __restrict__ A, const float* __restrict__ Bb,
             float* __restrict__ Cb, int M, int K,
             size_t aStrB, size_t bStrB, size_t sStr, size_t cStrB) {
    __shared__ float As[8][128];
    __shared__ float Bs[8][128];

    const int tid = threadIdx.x;
    const int n0 = blockIdx.x * 128;
    const int m0 = blockIdx.y * 128;
    const int b = blockIdx.z;

    const float* Ab = A + (size_t)b * aStrB;
    const float* Bbase = Bb + (size_t)b * bStrB;
    float* C = Cb + (size_t)b * cStrB;

    const int tx = tid & 15;        // n sub-tile
    const int ty = tid >> 4;        // m sub-tile

    const int aRow = tid >> 1;          // 0..127
    const int aCol = (tid & 1) * 4;     // 0 or 4
    const int bRow = tid >> 5;          // 0..7
    const int bCol = (tid & 31) * 4;    // 0..124

    unsigned long long acc[8][4];
#pragma unroll
    for (int i = 0; i < 8; i++)
#pragma unroll
        for (int j = 0; j < 4; j++) acc[i][j] = 0ull;

    for (int k0 = 0; k0 < K; k0 += 8) {
        float4 av = *(const float4*)(Ab + (size_t)(m0 + aRow) * K + k0 + aCol);
        int r = k0 + bRow;
        const float* brow = Bbase + (size_t)(r >> 7) * sStr + (size_t)(r & 127) * HWSZ;
        float4 bv = *(const float4*)(brow + n0 + bCol);

        __syncthreads();
        As[aCol + 0][aRow] = av.x;
        As[aCol + 1][aRow] = av.y;
        As[aCol + 2][aRow] = av.z;
        As[aCol + 3][aRow] = av.w;
        *(float4*)&Bs[bRow][bCol] = bv;
        __syncthreads();

#pragma unroll
        for (int kk = 0; kk < 8; kk++) {
            const float* ap = &As[kk][ty * 8];
            const unsigned long long* bp =
                (const unsigned long long*)&Bs[kk][tx * 8];
            unsigned long long b0 = bp[0], b1 = bp[1], b2 = bp[2], b3 = bp[3];
#pragma unroll
            for (int i = 0; i < 8; i++) {
                unsigned long long avp = pack2(ap[i]);
                fma2(acc[i][0], avp, b0);
                fma2(acc[i][1], avp, b1);
                fma2(acc[i][2], avp, b2);
                fma2(acc[i][3], avp, b3);
            }
        }
    }

#pragma unroll
    for (int i = 0; i < 8; i++) {
        float* cr = C + (size_t)(m0 + ty * 8 + i) * HWSZ + n0 + tx * 8;
        unsigned long long* cp = (unsigned long long*)cr;
#pragma unroll
        for (int j = 0; j < 4; j++) cp[j] = acc[i][j];
    }
}

// ---------------- fused multi-scale depthwise conv (3/5/7 in one pass) ------
__global__ void __launch_bounds__(256)
dwconv_kernel(const float* __restrict__ xq, const float* __restrict__ w3,
              const float* __restrict__ w5, const float* __restrict__ w7,
              float* __restrict__ D) {
    __shared__ float tile[22][72];
    __shared__ float s3[9], s5[25], s7[49];

    const int bc = blockIdx.z;           // b*384 + c
    const int b = bc / C3;
    const int c = bc % C3;
    const int x0 = blockIdx.x * 64;
    const int y0 = blockIdx.y * 16;
    const int tid = threadIdx.x;

    const float* src = xq + (size_t)bc * HWSZ;
    if (tid < 9) s3[tid] = w3[c * 9 + tid];
    if (tid < 25) s5[tid] = w5[c * 25 + tid];
    if (tid < 49) s7[tid] = w7[c * 49 + tid];

    for (int e = tid; e < 22 * 70; e += 256) {
        int iy = e / 70, ix = e % 70;
        int gy = y0 - 3 + iy, gx = x0 - 3 + ix;
        float v = 0.f;
        if (gy >= 0 && gy < IMG && gx >= 0 && gx < IMG)
            v = src[gy * IMG + gx];
        tile[iy][ix] = v;
    }
    __syncthreads();

    const int ty = tid >> 4;           // 0..15 rows
    const int tx = (tid & 15) * 4;     // 4-wide strip

    float a3[4] = {0, 0, 0, 0}, a5[4] = {0, 0, 0, 0}, a7[4] = {0, 0, 0, 0};
#pragma unroll
    for (int ky = 0; ky < 7; ky++) {
        float r[10];
#pragma unroll
        for (int j = 0; j < 10; j++) r[j] = tile[ty + ky][tx + j];
#pragma unroll
        for (int kx = 0; kx < 7; kx++) {
            float w = s7[ky * 7 + kx];
#pragma unroll
            for (int xi = 0; xi < 4; xi++) a7[xi] += r[kx + xi] * w;
        }
        if (ky >= 1 && ky <= 5) {
#pragma unroll
            for (int kx = 0; kx < 5; kx++) {
                float w = s5[(ky - 1) * 5 + kx];
#pragma unroll
                for (int xi = 0; xi < 4; xi++) a5[xi] += r[kx + 1 + xi] * w;
            }
        }
        if (ky >= 2 && ky <= 4) {
#pragma unroll
            for (int kx = 0; kx < 3; kx++) {
                float w = s3[(ky - 2) * 3 + kx];
#pragma unroll
                for (int xi = 0; xi < 4; xi++) a3[xi] += r[kx + 2 + xi] * w;
            }
        }
    }

    size_t obase = ((size_t)b * 3 * C3 + c) * HWSZ + (size_t)(y0 + ty) * IMG + (x0 + tx);
    *(float4*)&D[obase] = make_float4(a3[0], a3[1], a3[2], a3[3]);
    *(float4*)&D[obase + (size_t)C3 * HWSZ] = make_float4(a5[0], a5[1], a5[2], a5[3]);
    *(float4*)&D[obase + (size_t)2 * C3 * HWSZ] = make_float4(a7[0], a7[1], a7[2], a7[3]);
}

// ---------------- per-head Gram (q k^T) + sum-of-squares ----------------
__global__ void __launch_bounds__(256)
gram_kernel(const float* __restrict__ q, const float* __restrict__ k,
            float* __restrict__ G, float* __restrict__ SQ,
            float* __restrict__ SK) {
    __shared__ float qs[16][132];
    __shared__ float ks[16][132];
    __shared__ float Gs[16][16];
    __shared__ float Qss[16], Kss[16];

    const int tid = threadIdx.x;
    const int bh = blockIdx.y;             // b*8 + h
    const int nbase0 = blockIdx.x * 1024;  // 16-way n split

    const float* qh = q + (size_t)(bh * 16) * HWSZ;
    const float* kh = k + (size_t)(bh * 16) * HWSZ;

    Gs[tid >> 4][tid & 15] = 0.f;
    if (tid < 16) { Qss[tid] = 0.f; Kss[tid] = 0.f; }

    const int cg = tid & 3;
    const int dg = (tid >> 2) & 3;
    const int ns = tid >> 4;   // 0..15

    float acc[4][4];
#pragma unroll
    for (int i = 0; i < 4; i++)
#pragma unroll
        for (int j = 0; j < 4; j++) acc[i][j] = 0.f;
    float sq[4] = {0, 0, 0, 0}, sk[4] = {0, 0, 0, 0};

    for (int t = 0; t < 8; t++) {
        int nb = nbase0 + t * 128;
        __syncthreads();
        for (int e = tid; e < 16 * 32; e += 256) {
            int row = e >> 5, col = (e & 31) << 2;
            *(float4*)&qs[row][col] = *(const float4*)&qh[(size_t)row * HWSZ + nb + col];
            *(float4*)&ks[row][col] = *(const float4*)&kh[(size_t)row * HWSZ + nb + col];
        }
        __syncthreads();
#pragma unroll
        for (int nn = 0; nn < 8; nn++) {
            int n = ns * 8 + nn;
            float qv[4], kv[4];
#pragma unroll
            for (int i = 0; i < 4; i++) {
                qv[i] = qs[cg * 4 + i][n];
                kv[i] = ks[dg * 4 + i][n];
            }
#pragma unroll
            for (int i = 0; i < 4; i++)
#pragma unroll
                for (int j = 0; j < 4; j++) acc[i][j] += qv[i] * kv[j];
            if (dg == 0)
#pragma unroll
                for (int i = 0; i < 4; i++) sq[i] += qv[i] * qv[i];
            if (cg == 0)
#pragma unroll
                for (int i = 0; i < 4; i++) sk[i] += kv[i] * kv[i];
        }
    }
    __syncthreads();
#pragma unroll
    for (int i = 0; i < 4; i++)
#pragma unroll
        for (int j = 0; j < 4; j++)
            atomicAdd(&Gs[cg * 4 + i][dg * 4 + j], acc[i][j]);
    if (dg == 0)
#pragma unroll
        for (int i = 0; i < 4; i++) atomicAdd(&Qss[cg * 4 + i], sq[i]);
    if (cg == 0)
#pragma unroll
        for (int i = 0; i < 4; i++) atomicAdd(&Kss[dg * 4 + i], sk[i]);
    __syncthreads();

    atomicAdd(&G[(size_t)bh * 256 + tid], Gs[tid >> 4][tid & 15]);
    if (tid < 16) atomicAdd(&SQ[bh * 16 + tid], Qss[tid]);
    else if (tid < 32) atomicAdd(&SK[bh * 16 + tid - 16], Kss[tid - 16]);
}

// ---------------- normalize + temperature + softmax → attn ----------------
__global__ void attn_finalize(const float* __restrict__ G,
                              const float* __restrict__ SQ,
                              const float* __restrict__ SK,
                              const float* __restrict__ temp,
                              float* __restrict__ attn) {
    const int bh = blockIdx.x;
    const int h = bh & 7;
    const int c = threadIdx.x;
    if (c >= 16) return;
    float nq = fmaxf(sqrtf(SQ[bh * 16 + c]), 1e-12f);
    float t = temp[h];
    float s[16];
    float mx = -1e30f;
#pragma unroll
    for (int d = 0; d < 16; d++) {
        float nk = fmaxf(sqrtf(SK[bh * 16 + d]), 1e-12f);
        s[d] = G[bh * 256 + c * 16 + d] / (nq * nk) * t;
        mx = fmaxf(mx, s[d]);
    }
    float sum = 0.f;
#pragma unroll
    for (int d = 0; d < 16; d++) { s[d] = expf(s[d] - mx); sum += s[d]; }
    float inv = 1.f / sum;
#pragma unroll
    for (int d = 0; d < 16; d++) attn[bh * 256 + c * 16 + d] = s[d] * inv;
}

// ---------------- T1[b,m,r] = sum_d attn[b,h(m),m%16,d] * w_v[h*16+d, r] ----
__global__ void t1_kernel(const float* __restrict__ attn,
                          const float* __restrict__ wv,
                          float* __restrict__ T1) {
    const int bm = blockIdx.x;
    const int b = bm >> 7, m = bm & 127;
    const int h = m >> 4, cm = m & 15;
    __shared__ float a[16];
    if (threadIdx.x < 16)
        a[threadIdx.x] = attn[((b * 8 + h) * 16 + cm) * 16 + threadIdx.x];
    __syncthreads();
    const int r = threadIdx.x;  // 0..383
    float acc = 0.f;
#pragma unroll
    for (int d = 0; d < 16; d++) acc += a[d] * wv[(h * 16 + d) * C3 + r];
    T1[((size_t)b * CB + m) * C3 + r] = acc;
}

// ---------------- M[b,o,r] = sum_m w_out[o,m] * T1[b,m,r] ----------------
__global__ void m_kernel(const float* __restrict__ wout,
                         const float* __restrict__ T1,
                         float* __restrict__ Mo) {
    const int bo = blockIdx.x;
    const int b = bo >> 7, o = bo & 127;
    __shared__ float w[128];
    if (threadIdx.x < 128) w[threadIdx.x] = wout[o * 128 + threadIdx.x];
    __syncthreads();
    const int r = threadIdx.x;  // 0..383
    float acc = 0.f;
#pragma unroll 8
    for (int m = 0; m < 128; m++) acc += w[m] * T1[((size_t)b * CB + m) * C3 + r];
    Mo[((size_t)b * CB + o) * C3 + r] = acc;
}

// ---------------- zero the accumulators ----------------
__global__ void zero_stats(float* __restrict__ G, float* __restrict__ SQ,
                           float* __restrict__ SK) {
    int i = blockIdx.x * 256 + threadIdx.x;
    if (i < BATCH * HEADS * 256) G[i] = 0.f;
    if (i < BATCH * HEADS * 16) { SQ[i] = 0.f; SK[i] = 0.f; }
}

// ---------------- host launcher ----------------
extern "C" void kernel_launch(void* const* d_in, const int* in_sizes, int n_in,
                              void* d_out, int out_size) {
    const float* x     = (const float*)d_in[0];
    const float* w_qkv = (const float*)d_in[1];
    const float* w_dw3 = (const float*)d_in[2];
    const float* w_dw5 = (const float*)d_in[3];
    const float* w_dw7 = (const float*)d_in[4];
    const float* w_q   = (const float*)d_in[5];
    const float* w_k   = (const float*)d_in[6];
    const float* w_v   = (const float*)d_in[7];
    const float* w_out = (const float*)d_in[8];
    const float* temp  = (const float*)d_in[9];
    float* out = (float*)d_out;

    float *p_xq, *p_D, *p_q, *p_k, *p_gram, *p_ssq, *p_ssk, *p_attn, *p_T1, *p_M;
    cudaGetSymbolAddress((void**)&p_xq, g_xq);
    cudaGetSymbolAddress((void**)&p_D, g_D);
    cudaGetSymbolAddress((void**)&p_q, g_q);
    cudaGetSymbolAddress((void**)&p_k, g_k);
    cudaGetSymbolAddress((void**)&p_gram, g_gram);
    cudaGetSymbolAddress((void**)&p_ssq, g_ssq);
    cudaGetSymbolAddress((void**)&p_ssk, g_ssk);
    cudaGetSymbolAddress((void**)&p_attn, g_attn);
    cudaGetSymbolAddress((void**)&p_T1, g_T1);
    cudaGetSymbolAddress((void**)&p_M, g_M);

    // 0) zero gram accumulators
    zero_stats<<<64, 256>>>(p_gram, p_ssq, p_ssk);

    // 1) xq = w_qkv @ x   (M=384, K=128)
    sgemm_kernel<<<dim3(128, 3, BATCH), 256>>>(
        w_qkv, x, p_xq, 384, 128,
        (size_t)0, (size_t)128 * HWSZ, (size_t)128 * HWSZ, (size_t)C3 * HWSZ);

    // 2) fused multi-scale depthwise conv → D[b][scale][384][HW]
    dwconv_kernel<<<dim3(2, 8, BATCH * C3), 256>>>(p_xq, w_dw3, w_dw5, w_dw7, p_D);

    // 3) q = w_q @ D(q-part), k = w_k @ D(k-part)   (M=128, K=384)
    sgemm_kernel<<<dim3(128, 1, BATCH), 256>>>(
        w_q, p_D, p_q, 128, 384,
        (size_t)0, (size_t)3 * C3 * HWSZ, (size_t)C3 * HWSZ, (size_t)CB * HWSZ);
    sgemm_kernel<<<dim3(128, 1, BATCH), 256>>>(
        w_k, p_D + (size_t)CB * HWSZ, p_k, 128, 384,
        (size_t)0, (size_t)3 * C3 * HWSZ, (size_t)C3 * HWSZ, (size_t)CB * HWSZ);

    // 4) per-head Gram + sumsq, then softmax attn
    gram_kernel<<<dim3(16, BATCH * HEADS), 256>>>(p_q, p_k, p_gram, p_ssq, p_ssk);
    attn_finalize<<<BATCH * HEADS, 32>>>(p_gram, p_ssq, p_ssk, temp, p_attn);

    // 5) M_b = w_out @ blockdiag(attn) @ w_v
    t1_kernel<<<BATCH * CB, 384>>>(p_attn, w_v, p_T1);
    m_kernel<<<BATCH * CB, 384>>>(w_out, p_T1, p_M);

    // 6) out = M_b @ D(v-part)   (M=128, K=384) — v never materialized
    sgemm_kernel<<<dim3(128, 1, BATCH), 256>>>(
        p_M, p_D + (size_t)2 * CB * HWSZ, out, 128, 384,
        (size_t)CB * C3, (size_t)3 * C3 * HWSZ, (size_t)C3 * HWSZ, (size_t)CB * HWSZ);
}

// round 2
// speedup vs baseline: 1.0416x; 1.0416x over previous
#include <cuda_runtime.h>
#include <cstddef>
#include <math.h>

#define HWSZ 16384
#define IMG 128
#define CB 128
#define C3 384
#define BATCH 8
#define HEADS 8

typedef unsigned long long u64;

// ---------------- scratch (static device globals; no allocs) ----------------
__device__ float g_xq[(size_t)BATCH * C3 * HWSZ];      // [b][384][HW]
__device__ float g_D[(size_t)BATCH * 3 * C3 * HWSZ];   // [b][scale][384][HW]
__device__ float g_q[(size_t)BATCH * CB * HWSZ];       // [b][128][HW]
__device__ float g_k[(size_t)BATCH * CB * HWSZ];
__device__ float g_gram[BATCH * HEADS * 16 * 16];
__device__ float g_ssq[BATCH * HEADS * 16];
__device__ float g_ssk[BATCH * HEADS * 16];
__device__ float g_attn[BATCH * HEADS * 16 * 16];
__device__ float g_T1[BATCH * CB * C3];
__device__ float g_M[BATCH * CB * C3];

// ---------------- packed fp32x2 helpers (Blackwell f32x2 pipe) --------------
__device__ __forceinline__ u64 pack2(float x) {
    u64 r;
    asm("mov.b64 %0, {%1, %1};" : "=l"(r) : "f"(x));
    return r;
}
__device__ __forceinline__ void fma2(u64& d, u64 a, u64 b) {
    asm("fma.rn.f32x2 %0, %1, %2, %0;" : "+l"(d) : "l"(a), "l"(b));
}

// ---------------- generic SGEMM: C[b,m,n] = sum_r A[m,r] * Brow(r)[n] -------
// B row r of batch z lives at: Bb + z*bStrB + (r>>7)*sStr + (r&127)*HWSZ
// A (weights) at A + z*aStrB, row-major [M,K].
// Double-buffered smem; A pre-packed (duplicated f32x2) at staging time.
__global__ void __launch_bounds__(256)
sgemm_kernel(const float* __restrict__ A, const float* __restrict__ Bb,
             float* __restrict__ Cb, int M, int K,
             size_t aStrB, size_t bStrB, size_t sStr, size_t cStrB) {
    __shared__ u64 As[2][8][128];     // [buf][k][m]  (16 KB)
    __shared__ float Bs[2][8][136];   // [buf][k][n]  padded to 16B mult (8.5 KB)

    const int tid = threadIdx.x;
    const int n0 = blockIdx.x * 128;
    const int m0 = blockIdx.y * 128;
    const int b = blockIdx.z;

    const float* Ab = A + (size_t)b * aStrB;
    const float* Bbase = Bb + (size_t)b * bStrB;
    float* C = Cb + (size_t)b * cStrB;

    const int tx = tid & 15;        // n sub-tile (8 wide)
    const int ty = tid >> 4;        // m sub-tile (8 tall)

    const int aRow = tid >> 1;          // 0..127
    const int aCol = (tid & 1) * 4;     // 0 or 4
    const int bRow = tid >> 5;          // 0..7
    const int bCol = (tid & 31) * 4;    // 0..124

    u64 acc[8][4];
#pragma unroll
    for (int i = 0; i < 8; i++)
#pragma unroll
        for (int j = 0; j < 4; j++) acc[i][j] = 0ull;

    // ---- stage tile 0 ----
    {
        float4 av = *(const float4*)(Ab + (size_t)(m0 + aRow) * K + aCol);
        const float* brow = Bbase + (size_t)bRow * HWSZ;  // r = bRow < 8
        float4 bv = *(const float4*)(brow + n0 + bCol);
        As[0][aCol + 0][aRow] = pack2(av.x);
        As[0][aCol + 1][aRow] = pack2(av.y);
        As[0][aCol + 2][aRow] = pack2(av.z);
        As[0][aCol + 3][aRow] = pack2(av.w);
        *(float4*)&Bs[0][bRow][bCol] = bv;
    }
    __syncthreads();

    int buf = 0;
#pragma unroll 1
    for (int k0 = 0; k0 < K; k0 += 8) {
        const bool more = (k0 + 8) < K;
        float4 av, bv;
        if (more) {
            av = *(const float4*)(Ab + (size_t)(m0 + aRow) * K + (k0 + 8) + aCol);
            int r = k0 + 8 + bRow;
            const float* brow =
                Bbase + (size_t)(r >> 7) * sStr + (size_t)(r & 127) * HWSZ;
            bv = *(const float4*)(brow + n0 + bCol);
        }

#pragma unroll
        for (int kk = 0; kk < 8; kk++) {
            const ulonglong2* apq = (const ulonglong2*)&As[buf][kk][ty * 8];
            ulonglong2 A0 = apq[0], A1 = apq[1], A2 = apq[2], A3 = apq[3];
            const ulonglong2* bpq = (const ulonglong2*)&Bs[buf][kk][tx * 8];
            ulonglong2 B0 = bpq[0], B1 = bpq[1];
            u64 a[8] = {A0.x, A0.y, A1.x, A1.y, A2.x, A2.y, A3.x, A3.y};
#pragma unroll
            for (int i = 0; i < 8; i++) {
                fma2(acc[i][0], a[i], B0.x);
                fma2(acc[i][1], a[i], B0.y);
                fma2(acc[i][2], a[i], B1.x);
                fma2(acc[i][3], a[i], B1.y);
            }
        }

        if (more) {
            int nb = buf ^ 1;
            As[nb][aCol + 0][aRow] = pack2(av.x);
            As[nb][aCol + 1][aRow] = pack2(av.y);
            As[nb][aCol + 2][aRow] = pack2(av.z);
            As[nb][aCol + 3][aRow] = pack2(av.w);
            *(float4*)&Bs[nb][bRow][bCol] = bv;
            __syncthreads();
            buf = nb;
        }
    }

#pragma unroll
    for (int i = 0; i < 8; i++) {
        float* cr = C + (size_t)(m0 + ty * 8 + i) * HWSZ + n0 + tx * 8;
        u64* cp = (u64*)cr;
#pragma unroll
        for (int j = 0; j < 4; j++) cp[j] = acc[i][j];
    }
}

// ---------------- fused multi-scale depthwise conv (3/5/7 in one pass) ------
__global__ void __launch_bounds__(256)
dwconv_kernel(const float* __restrict__ xq, const float* __restrict__ w3,
              const float* __restrict__ w5, const float* __restrict__ w7,
              float* __restrict__ D) {
    __shared__ float tile[22][72];
    __shared__ float s3[9], s5[25], s7[49];

    const int bc = blockIdx.z;           // b*384 + c
    const int b = bc / C3;
    const int c = bc % C3;
    const int x0 = blockIdx.x * 64;
    const int y0 = blockIdx.y * 16;
    const int tid = threadIdx.x;

    const float* src = xq + (size_t)bc * HWSZ;
    if (tid < 9) s3[tid] = w3[c * 9 + tid];
    if (tid < 25) s5[tid] = w5[c * 25 + tid];
    if (tid < 49) s7[tid] = w7[c * 49 + tid];

    for (int e = tid; e < 22 * 70; e += 256) {
        int iy = e / 70, ix = e % 70;
        int gy = y0 - 3 + iy, gx = x0 - 3 + ix;
        float v = 0.f;
        if (gy >= 0 && gy < IMG && gx >= 0 && gx < IMG)
            v = src[gy * IMG + gx];
        tile[iy][ix] = v;
    }
    __syncthreads();

    const int ty = tid >> 4;           // 0..15 rows
    const int tx = (tid & 15) * 4;     // 4-wide strip

    float a3[4] = {0, 0, 0, 0}, a5[4] = {0, 0, 0, 0}, a7[4] = {0, 0, 0, 0};
#pragma unroll
    for (int ky = 0; ky < 7; ky++) {
        float r[10];
#pragma unroll
        for (int j = 0; j < 10; j++) r[j] = tile[ty + ky][tx + j];
#pragma unroll
        for (int kx = 0; kx < 7; kx++) {
            float w = s7[ky * 7 + kx];
#pragma unroll
            for (int xi = 0; xi < 4; xi++) a7[xi] += r[kx + xi] * w;
        }
        if (ky >= 1 && ky <= 5) {
#pragma unroll
            for (int kx = 0; kx < 5; kx++) {
                float w = s5[(ky - 1) * 5 + kx];
#pragma unroll
                for (int xi = 0; xi < 4; xi++) a5[xi] += r[kx + 1 + xi] * w;
            }
        }
        if (ky >= 2 && ky <= 4) {
#pragma unroll
            for (int kx = 0; kx < 3; kx++) {
                float w = s3[(ky - 2) * 3 + kx];
#pragma unroll
                for (int xi = 0; xi < 4; xi++) a3[xi] += r[kx + 2 + xi] * w;
            }
        }
    }

    size_t obase = ((size_t)b * 3 * C3 + c) * HWSZ + (size_t)(y0 + ty) * IMG + (x0 + tx);
    *(float4*)&D[obase] = make_float4(a3[0], a3[1], a3[2], a3[3]);
    *(float4*)&D[obase + (size_t)C3 * HWSZ] = make_float4(a5[0], a5[1], a5[2], a5[3]);
    *(float4*)&D[obase + (size_t)2 * C3 * HWSZ] = make_float4(a7[0], a7[1], a7[2], a7[3]);
}

// ---------------- per-head Gram (q k^T) + sum-of-squares ----------------
__global__ void __launch_bounds__(256)
gram_kernel(const float* __restrict__ q, const float* __restrict__ k,
            float* __restrict__ G, float* __restrict__ SQ,
            float* __restrict__ SK) {
    __shared__ float qs[16][132];
    __shared__ float ks[16][132];
    __shared__ float Gs[16][16];
    __shared__ float Qss[16], Kss[16];

    const int tid = threadIdx.x;
    const int bh = blockIdx.y;             // b*8 + h
    const int nbase0 = blockIdx.x * 1024;  // 16-way n split

    const float* qh = q + (size_t)(bh * 16) * HWSZ;
    const float* kh = k + (size_t)(bh * 16) * HWSZ;

    Gs[tid >> 4][tid & 15] = 0.f;
    if (tid < 16) { Qss[tid] = 0.f; Kss[tid] = 0.f; }

    const int cg = tid & 3;
    const int dg = (tid >> 2) & 3;
    const int ns = tid >> 4;   // 0..15

    float acc[4][4];
#pragma unroll
    for (int i = 0; i < 4; i++)
#pragma unroll
        for (int j = 0; j < 4; j++) acc[i][j] = 0.f;
    float sq[4] = {0, 0, 0, 0}, sk[4] = {0, 0, 0, 0};

    for (int t = 0; t < 8; t++) {
        int nb = nbase0 + t * 128;
        __syncthreads();
        for (int e = tid; e < 16 * 32; e += 256) {
            int row = e >> 5, col = (e & 31) << 2;
            *(float4*)&qs[row][col] = *(const float4*)&qh[(size_t)row * HWSZ + nb + col];
            *(float4*)&ks[row][col] = *(const float4*)&kh[(size_t)row * HWSZ + nb + col];
        }
        __syncthreads();
#pragma unroll
        for (int nn = 0; nn < 8; nn++) {
            int n = ns * 8 + nn;
            float qv[4], kv[4];
#pragma unroll
            for (int i = 0; i < 4; i++) {
                qv[i] = qs[cg * 4 + i][n];
                kv[i] = ks[dg * 4 + i][n];
            }
#pragma unroll
            for (int i = 0; i < 4; i++)
#pragma unroll
                for (int j = 0; j < 4; j++) acc[i][j] += qv[i] * kv[j];
            if (dg == 0)
#pragma unroll
                for (int i = 0; i < 4; i++) sq[i] += qv[i] * qv[i];
            if (cg == 0)
#pragma unroll
                for (int i = 0; i < 4; i++) sk[i] += kv[i] * kv[i];
        }
    }
    __syncthreads();
#pragma unroll
    for (int i = 0; i < 4; i++)
#pragma unroll
        for (int j = 0; j < 4; j++)
            atomicAdd(&Gs[cg * 4 + i][dg * 4 + j], acc[i][j]);
    if (dg == 0)
#pragma unroll
        for (int i = 0; i < 4; i++) atomicAdd(&Qss[cg * 4 + i], sq[i]);
    if (cg == 0)
#pragma unroll
        for (int i = 0; i < 4; i++) atomicAdd(&Kss[dg * 4 + i], sk[i]);
    __syncthreads();

    atomicAdd(&G[(size_t)bh * 256 + tid], Gs[tid >> 4][tid & 15]);
    if (tid < 16) atomicAdd(&SQ[bh * 16 + tid], Qss[tid]);
    else if (tid < 32) atomicAdd(&SK[bh * 16 + tid - 16], Kss[tid - 16]);
}

// ---------------- normalize + temperature + softmax → attn ----------------
__global__ void attn_finalize(const float* __restrict__ G,
                              const float* __restrict__ SQ,
                              const float* __restrict__ SK,
                              const float* __restrict__ temp,
                              float* __restrict__ attn) {
    const int bh = blockIdx.x;
    const int h = bh & 7;
    const int c = threadIdx.x;
    if (c >= 16) return;
    float nq = fmaxf(sqrtf(SQ[bh * 16 + c]), 1e-12f);
    float t = temp[h];
    float s[16];
    float mx = -1e30f;
#pragma unroll
    for (int d = 0; d < 16; d++) {
        float nk = fmaxf(sqrtf(SK[bh * 16 + d]), 1e-12f);
        s[d] = G[bh * 256 + c * 16 + d] / (nq * nk) * t;
        mx = fmaxf(mx, s[d]);
    }
    float sum = 0.f;
#pragma unroll
    for (int d = 0; d < 16; d++) { s[d] = expf(s[d] - mx); sum += s[d]; }
    float inv = 1.f / sum;
#pragma unroll
    for (int d = 0; d < 16; d++) attn[bh * 256 + c * 16 + d] = s[d] * inv;
}

// ---------------- T1[b,m,r] = sum_d attn[b,h(m),m%16,d] * w_v[h*16+d, r] ----
__global__ void t1_kernel(const float* __restrict__ attn,
                          const float* __restrict__ wv,
                          float* __restrict__ T1) {
    const int bm = blockIdx.x;
    const int b = bm >> 7, m = bm & 127;
    const int h = m >> 4, cm = m & 15;
    __shared__ float a[16];
    if (threadIdx.x < 16)
        a[threadIdx.x] = attn[((b * 8 + h) * 16 + cm) * 16 + threadIdx.x];
    __syncthreads();
    const int r = threadIdx.x;  // 0..383
    float acc = 0.f;
#pragma unroll
    for (int d = 0; d < 16; d++) acc += a[d] * wv[(h * 16 + d) * C3 + r];
    T1[((size_t)b * CB + m) * C3 + r] = acc;
}

// ---------------- M[b,o,r] = sum_m w_out[o,m] * T1[b,m,r] ----------------
__global__ void m_kernel(const float* __restrict__ wout,
                         const float* __restrict__ T1,
                         float* __restrict__ Mo) {
    const int bo = blockIdx.x;
    const int b = bo >> 7, o = bo & 127;
    __shared__ float w[128];
    if (threadIdx.x < 128) w[threadIdx.x] = wout[o * 128 + threadIdx.x];
    __syncthreads();
    const int r = threadIdx.x;  // 0..383
    float acc = 0.f;
#pragma unroll 8
    for (int m = 0; m < 128; m++) acc += w[m] * T1[((size_t)b * CB + m) * C3 + r];
    Mo[((size_t)b * CB + o) * C3 + r] = acc;
}

// ---------------- zero the accumulators ----------------
__global__ void zero_stats(float* __restrict__ G, float* __restrict__ SQ,
                           float* __restrict__ SK) {
    int i = blockIdx.x * 256 + threadIdx.x;
    if (i < BATCH * HEADS * 256) G[i] = 0.f;
    if (i < BATCH * HEADS * 16) { SQ[i] = 0.f; SK[i] = 0.f; }
}

// ---------------- host launcher ----------------
extern "C" void kernel_launch(void* const* d_in, const int* in_sizes, int n_in,
                              void* d_out, int out_size) {
    const float* x     = (const float*)d_in[0];
    const float* w_qkv = (const float*)d_in[1];
    const float* w_dw3 = (const float*)d_in[2];
    const float* w_dw5 = (const float*)d_in[3];
    const float* w_dw7 = (const float*)d_in[4];
    const float* w_q   = (const float*)d_in[5];
    const float* w_k   = (const float*)d_in[6];
    const float* w_v   = (const float*)d_in[7];
    const float* w_out = (const float*)d_in[8];
    const float* temp  = (const float*)d_in[9];
    float* out = (float*)d_out;

    float *p_xq, *p_D, *p_q, *p_k, *p_gram, *p_ssq, *p_ssk, *p_attn, *p_T1, *p_M;
    cudaGetSymbolAddress((void**)&p_xq, g_xq);
    cudaGetSymbolAddress((void**)&p_D, g_D);
    cudaGetSymbolAddress((void**)&p_q, g_q);
    cudaGetSymbolAddress((void**)&p_k, g_k);
    cudaGetSymbolAddress((void**)&p_gram, g_gram);
    cudaGetSymbolAddress((void**)&p_ssq, g_ssq);
    cudaGetSymbolAddress((void**)&p_ssk, g_ssk);
    cudaGetSymbolAddress((void**)&p_attn, g_attn);
    cudaGetSymbolAddress((void**)&p_T1, g_T1);
    cudaGetSymbolAddress((void**)&p_M, g_M);

    // 0) zero gram accumulators
    zero_stats<<<64, 256>>>(p_gram, p_ssq, p_ssk);

    // 1) xq = w_qkv @ x   (M=384, K=128)
    sgemm_kernel<<<dim3(128, 3, BATCH), 256>>>(
        w_qkv, x, p_xq, 384, 128,
        (size_t)0, (size_t)128 * HWSZ, (size_t)128 * HWSZ, (size_t)C3 * HWSZ);

    // 2) fused multi-scale depthwise conv → D[b][scale][384][HW]
    dwconv_kernel<<<dim3(2, 8, BATCH * C3), 256>>>(p_xq, w_dw3, w_dw5, w_dw7, p_D);

    // 3) q = w_q @ D(q-part), k = w_k @ D(k-part)   (M=128, K=384)
    sgemm_kernel<<<dim3(128, 1, BATCH), 256>>>(
        w_q, p_D, p_q, 128, 384,
        (size_t)0, (size_t)3 * C3 * HWSZ, (size_t)C3 * HWSZ, (size_t)CB * HWSZ);
    sgemm_kernel<<<dim3(128, 1, BATCH), 256>>>(
        w_k, p_D + (size_t)CB * HWSZ, p_k, 128, 384,
        (size_t)0, (size_t)3 * C3 * HWSZ, (size_t)C3 * HWSZ, (size_t)CB * HWSZ);

    // 4) per-head Gram + sumsq, then softmax attn
    gram_kernel<<<dim3(16, BATCH * HEADS), 256>>>(p_q, p_k, p_gram, p_ssq, p_ssk);
    attn_finalize<<<BATCH * HEADS, 32>>>(p_gram, p_ssq, p_ssk, temp, p_attn);

    // 5) M_b = w_out @ blockdiag(attn) @ w_v
    t1_kernel<<<BATCH * CB, 384>>>(p_attn, w_v, p_T1);
    m_kernel<<<BATCH * CB, 384>>>(w_out, p_T1, p_M);

    // 6) out = M_b @ D(v-part)   (M=128, K=384) — v never materialized
    sgemm_kernel<<<dim3(128, 1, BATCH), 256>>>(
        p_M, p_D + (size_t)2 * CB * HWSZ, out, 128, 384,
        (size_t)CB * C3, (size_t)3 * C3 * HWSZ, (size_t)C3 * HWSZ, (size_t)CB * HWSZ);
}